// round 15
// baseline (speedup 1.0000x reference)
#include <cuda_runtime.h>
#include <math.h>

typedef unsigned long long ULL;

// ---------- packed f32x2 helpers (double-rate fp32 FMA path on sm_103a) ----------
__device__ __forceinline__ ULL fma2(ULL a, ULL b, ULL c) {
    ULL d;
    asm("fma.rn.f32x2 %0, %1, %2, %3;" : "=l"(d) : "l"(a), "l"(b), "l"(c));
    return d;
}
__device__ __forceinline__ ULL pack2(float lo, float hi) {
    ULL r;
    asm("mov.b64 %0, {%1, %2};" : "=l"(r) : "f"(lo), "f"(hi));
    return r;
}
__device__ __forceinline__ ULL dup2(float v) { return pack2(v, v); }
__device__ __forceinline__ void unpack2(ULL v, float& lo, float& hi) {
    asm("mov.b64 {%0, %1}, %2;" : "=f"(lo), "=f"(hi) : "l"(v));
}

// ---------- cp.async helpers ----------
__device__ __forceinline__ void cp16(float* dst_sm, const float* src_g) {
    unsigned d = (unsigned)__cvta_generic_to_shared(dst_sm);
    asm volatile("cp.async.cg.shared.global [%0], [%1], 16;" :: "r"(d), "l"(src_g) : "memory");
}
__device__ __forceinline__ void cp_commit() {
    asm volatile("cp.async.commit_group;" ::: "memory");
}
template<int N> __device__ __forceinline__ void cp_wait() {
    asm volatile("cp.async.wait_group %0;" :: "n"(N) : "memory");
}

// ---------- global scratch (no allocation allowed) ----------
#define NBOX 4096
__device__ float g_c2[NBOX * 2048];   // conv2 output, flattened per box
__device__ float g_h1[NBOX * 512];    // dense1 output
__device__ float g_h2[NBOX * 512];    // dense2 output

// ---------- kernel 1: fused crop_and_resize + conv1 + conv2 (one block per box) ----------
// 512 threads/block (1 block/SM -> 4 warps/SMSP for latency hiding).
// smem layout (floats). Pixel strides PADDED to break bank congruence:
//   crop: 17x17 pixels, stride 68  (19652 floats); reused as conv2 weight buf0 (16384)
//   c1:   9x9 pixels,  stride 132 (10692 floats); reused as conv2 partial buffer (4x2048)
//   w1:   conv1 weight double buffer (2 x 8192);   reused as conv2 weight buf1 (16384)
//   pix:  per-pixel crop params (256 x 8)
#define CROP_STRIDE 68
#define C1_STRIDE   132
#define CROP_OFF 0
#define C1_OFF   19652
#define W1_OFF   30344
#define PIX_OFF  46728
#define SMEM_FLOATS 48776
#define SMEM_BYTES  (SMEM_FLOATS * 4)
#define CC_THREADS 512

__global__ __launch_bounds__(CC_THREADS, 1)
void crop_conv_kernel(const float* __restrict__ features,
                      const float* __restrict__ proposal,
                      const float* __restrict__ bboxes,
                      const int*   __restrict__ box_idx,
                      const float* __restrict__ c1w,
                      const float* __restrict__ c1b,
                      const float* __restrict__ c2w,
                      const float* __restrict__ c2b)
{
    extern __shared__ float sm[];
    const int box = blockIdx.x;
    const int t   = threadIdx.x;

    // ---- prologue: prefetch conv1 weight slice 0 (hidden behind crop gather) ----
    {
        float* dst = sm + W1_OFF;
        #pragma unroll
        for (int q = 0; q < 4; q++) { int f = t + q * CC_THREADS; cp16(dst + f * 4, c1w + f * 4); }
        cp_commit();
    }

    const float by1 = bboxes[box * 4 + 0];
    const float bx1 = bboxes[box * 4 + 1];
    const float by2 = bboxes[box * 4 + 2];
    const float bx2 = bboxes[box * 4 + 3];
    const int   bimg = box_idx[box];

    // ---- Phase 0: zero ONLY padding cells; compute per-pixel sample params ----
    {
        // crop row 16 (17 pixels): 17*68 = 1156 floats, contiguous at pixel 272
        for (int i = t; i < 1156; i += CC_THREADS) sm[CROP_OFF + 272 * CROP_STRIDE + i] = 0.f;
        // crop col 16, rows 0..15: 16*68 = 1088 floats
        for (int i = t; i < 1088; i += CC_THREADS) {
            int gy = i / CROP_STRIDE, j = i - gy * CROP_STRIDE;
            sm[CROP_OFF + (gy * 17 + 16) * CROP_STRIDE + j] = 0.f;
        }
        // c1 row 8 (9 pixels): 9*132 = 1188 floats, contiguous at pixel 72
        for (int i = t; i < 1188; i += CC_THREADS) sm[C1_OFF + 72 * C1_STRIDE + i] = 0.f;
        // c1 col 8, rows 0..7: 8*132 = 1056 floats
        for (int i = t; i < 1056; i += CC_THREADS) {
            int gy = i / C1_STRIDE, j = i - gy * C1_STRIDE;
            sm[C1_OFF + (gy * 9 + 8) * C1_STRIDE + j] = 0.f;
        }
    }
    if (t < 256) {
        const int gy = t >> 4, gx = t & 15;
        float fy = (by1 + (gy * (1.0f / 15.0f)) * (by2 - by1)) * 511.0f;
        float fx = (bx1 + (gx * (1.0f / 15.0f)) * (bx2 - bx1)) * 511.0f;
        float fy0 = floorf(fy), fx0 = floorf(fx);
        float wy = fy - fy0, wx = fx - fx0;
        int iy0 = min(max((int)fy0, 0), 511); int iy1 = min(iy0 + 1, 511);
        int ix0 = min(max((int)fx0, 0), 511); int ix1 = min(ix0 + 1, 511);
        const float* pr = proposal + (size_t)bimg * 512 * 512;
        float p00 = pr[iy0 * 512 + ix0], p01 = pr[iy0 * 512 + ix1];
        float p10 = pr[iy1 * 512 + ix0], p11 = pr[iy1 * 512 + ix1];
        float ptop = p00 + wx * (p01 - p00);
        float pbot = p10 + wx * (p11 - p10);
        float pv = ptop + wy * (pbot - ptop);
        float* px = sm + PIX_OFF + t * 8;
        px[0] = __int_as_float(iy0); px[1] = __int_as_float(iy1);
        px[2] = __int_as_float(ix0); px[3] = __int_as_float(ix1);
        px[4] = wy; px[5] = wx; px[6] = pv;
    }
    __syncthreads();

    // ---- Phase 1: gather features (coalesced: 16 lanes span the 64 channels) ----
    {
        const int c = (t & 15) * 4;
        const float* fbase = features + (size_t)bimg * 512 * 512 * 64 + c;
        #pragma unroll 4
        for (int pass = 0; pass < 8; pass++) {
            int p = pass * 32 + (t >> 4);
            const float* px = sm + PIX_OFF + p * 8;
            int iy0 = __float_as_int(px[0]), iy1 = __float_as_int(px[1]);
            int ix0 = __float_as_int(px[2]), ix1 = __float_as_int(px[3]);
            float wy = px[4], wx = px[5], pv = px[6];
            float4 v00 = *(const float4*)(fbase + ((size_t)iy0 * 512 + ix0) * 64);
            float4 v01 = *(const float4*)(fbase + ((size_t)iy0 * 512 + ix1) * 64);
            float4 v10 = *(const float4*)(fbase + ((size_t)iy1 * 512 + ix0) * 64);
            float4 v11 = *(const float4*)(fbase + ((size_t)iy1 * 512 + ix1) * 64);
            float4 r;
            {
                float tp, bt;
                tp = v00.x + wx * (v01.x - v00.x); bt = v10.x + wx * (v11.x - v10.x);
                r.x = (tp + wy * (bt - tp)) * pv;
                tp = v00.y + wx * (v01.y - v00.y); bt = v10.y + wx * (v11.y - v10.y);
                r.y = (tp + wy * (bt - tp)) * pv;
                tp = v00.z + wx * (v01.z - v00.z); bt = v10.z + wx * (v11.z - v10.z);
                r.z = (tp + wy * (bt - tp)) * pv;
                tp = v00.w + wx * (v01.w - v00.w); bt = v10.w + wx * (v11.w - v10.w);
                r.w = (tp + wy * (bt - tp)) * pv;
            }
            int gy = p >> 4, gx = p & 15;
            *(float4*)(sm + CROP_OFF + (gy * 17 + gx) * CROP_STRIDE + c) = r;
        }
    }

    // ---- Phase 2: conv1 (stride 2, SAME pad bottom/right) as 9 smem GEMMs.
    //      512 threads: 2 px x 8 co per thread. Warp: 8 pxg x 4 cog. ----
    const int lane = t & 31, wrp = t >> 5;           // wrp 0..15
    const int pxg = (lane & 7) | ((wrp & 3) << 3);   // 0..31 (2 pixels each)
    const int cog = (lane >> 3) | ((wrp >> 2) << 2); // 0..15 (8 channels each)
    const int co0 = cog * 8;
    int oyv[2], oxv[2];
    #pragma unroll
    for (int i = 0; i < 2; i++) { int p = pxg * 2 + i; oyv[i] = p >> 3; oxv[i] = p & 7; }

    ULL acc[2][4];
    #pragma unroll
    for (int jp = 0; jp < 4; jp++) {
        ULL bb = pack2(c1b[co0 + 2 * jp], c1b[co0 + 2 * jp + 1]);
        #pragma unroll
        for (int i = 0; i < 2; i++) acc[i][jp] = bb;
    }

    #define CONV1_STEP(u, comp)                                                   \
        {                                                                         \
            const ulonglong2* wp = (const ulonglong2*)(wb + (ci4 + u) * 128 + co0);\
            ulonglong2 w01 = wp[0];                                               \
            ulonglong2 w23 = wp[1];                                               \
            _Pragma("unroll")                                                     \
            for (int i = 0; i < 2; i++) {                                         \
                ULL a2 = dup2(av[i].comp);                                        \
                acc[i][0] = fma2(a2, w01.x, acc[i][0]);                           \
                acc[i][1] = fma2(a2, w01.y, acc[i][1]);                           \
                acc[i][2] = fma2(a2, w23.x, acc[i][2]);                           \
                acc[i][3] = fma2(a2, w23.y, acc[i][3]);                           \
            }                                                                     \
        }

    for (int s = 0; s < 9; s++) {
        if (s < 8) {
            const float* src = c1w + (s + 1) * 8192;
            float* dst = sm + W1_OFF + ((s + 1) & 1) * 8192;
            #pragma unroll
            for (int q = 0; q < 4; q++) { int f = t + q * CC_THREADS; cp16(dst + f * 4, src + f * 4); }
            cp_commit();
            cp_wait<1>();
        } else {
            cp_wait<0>();
        }
        __syncthreads();

        const float* wb = sm + W1_OFF + (s & 1) * 8192;
        const int ky = s / 3, kx = s - 3 * (s / 3);
        int pb[2];
        #pragma unroll
        for (int i = 0; i < 2; i++)
            pb[i] = ((oyv[i] * 2 + ky) * 17 + (oxv[i] * 2 + kx)) * CROP_STRIDE;
        #pragma unroll 4
        for (int ci4 = 0; ci4 < 64; ci4 += 4) {
            float4 av[2];
            #pragma unroll
            for (int i = 0; i < 2; i++)
                av[i] = *(const float4*)(sm + CROP_OFF + pb[i] + ci4);
            CONV1_STEP(0, x)
            CONV1_STEP(1, y)
            CONV1_STEP(2, z)
            CONV1_STEP(3, w)
        }
        __syncthreads();
    }
    // relu + store into zero-padded 9x9 (stride 132) c1
    #pragma unroll
    for (int i = 0; i < 2; i++) {
        float* dst = sm + C1_OFF + (oyv[i] * 9 + oxv[i]) * C1_STRIDE + co0;
        #pragma unroll
        for (int jp = 0; jp < 4; jp++) {
            float v0, v1; unpack2(acc[i][jp], v0, v1);
            dst[2 * jp]     = fmaxf(v0, 0.f);
            dst[2 * jp + 1] = fmaxf(v1, 0.f);
        }
    }

    // ---- Phase 3: conv2 as 9 smem GEMMs, 4-way K-split, double-buffered weights ----
    // prefetch conv2 slice 0 into crop region (all conv1 reads of crop are done)
    {
        float* dst = sm + CROP_OFF;
        #pragma unroll
        for (int q = 0; q < 8; q++) { int f = t + q * CC_THREADS; cp16(dst + f * 4, c2w + f * 4); }
        cp_commit();
    }

    const int ks  = t >> 7;                           // K-split 0..3
    const int rem = t & 127;
    const int pg2 = lane & 3;                         // 4 pixel groups -> broadcast a-loads
    const int cg2 = (lane >> 2) | ((rem >> 5) << 3);  // 0..31 (4 channels each)
    const int co2 = cg2 * 4;
    int oy2[4], ox2[4];
    #pragma unroll
    for (int i = 0; i < 4; i++) { int p = pg2 * 4 + i; oy2[i] = p >> 2; ox2[i] = p & 3; }

    ULL ac2[4][2];
    #pragma unroll
    for (int i = 0; i < 4; i++)
        #pragma unroll
        for (int jp = 0; jp < 2; jp++) ac2[i][jp] = 0ull;

    #define CONV2_STEP(u, comp)                                                   \
        {                                                                         \
            const ulonglong2* wp = (const ulonglong2*)(wb + (ciw + u) * 128 + co2);\
            ulonglong2 w01 = wp[0];                                               \
            _Pragma("unroll")                                                     \
            for (int i = 0; i < 4; i++) {                                         \
                ULL a2 = dup2(av[i].comp);                                        \
                ac2[i][0] = fma2(a2, w01.x, ac2[i][0]);                           \
                ac2[i][1] = fma2(a2, w01.y, ac2[i][1]);                           \
            }                                                                     \
        }

    const int cibeg = ks * 32;
    for (int s = 0; s < 9; s++) {
        if (s < 8) {
            const float* src = c2w + (s + 1) * 16384;
            float* dst = sm + (((s + 1) & 1) ? W1_OFF : CROP_OFF);
            #pragma unroll
            for (int q = 0; q < 8; q++) { int f = t + q * CC_THREADS; cp16(dst + f * 4, src + f * 4); }
            cp_commit();
            cp_wait<1>();
        } else {
            cp_wait<0>();
        }
        __syncthreads();   // at s=0 this also publishes the c1 relu-stores

        const float* wb = sm + ((s & 1) ? W1_OFF : CROP_OFF);
        const int ky = s / 3, kx = s - 3 * (s / 3);
        int pb[4];
        #pragma unroll
        for (int i = 0; i < 4; i++)
            pb[i] = ((oy2[i] * 2 + ky) * 9 + (ox2[i] * 2 + kx)) * C1_STRIDE + cibeg;
        #pragma unroll 4
        for (int ci4 = 0; ci4 < 32; ci4 += 4) {
            float4 av[4];
            #pragma unroll
            for (int i = 0; i < 4; i++)
                av[i] = *(const float4*)(sm + C1_OFF + pb[i] + ci4);
            const int ciw = cibeg + ci4;   // absolute weight row
            CONV2_STEP(0, x)
            CONV2_STEP(1, y)
            CONV2_STEP(2, z)
            CONV2_STEP(3, w)
        }
        __syncthreads();
    }
    // write K-split partials into the (now dead) c1 region: 4 x 2048
    #pragma unroll
    for (int i = 0; i < 4; i++) {
        int px = pg2 * 4 + i;
        float* dst = sm + C1_OFF + ks * 2048 + px * 128 + co2;
        #pragma unroll
        for (int jp = 0; jp < 2; jp++) {
            float v0, v1; unpack2(ac2[i][jp], v0, v1);
            dst[2 * jp] = v0; dst[2 * jp + 1] = v1;
        }
    }
    __syncthreads();
    {   // reduce + bias + relu -> flattened conv2 output in global
        float* c2out = g_c2 + (size_t)box * 2048;
        #pragma unroll
        for (int r = 0; r < 4; r++) {
            int o = t * 4 + r;
            float v = sm[C1_OFF + o] + sm[C1_OFF + 2048 + o]
                    + sm[C1_OFF + 4096 + o] + sm[C1_OFF + 6144 + o] + c2b[o & 127];
            c2out[o] = fmaxf(v, 0.f);
        }
    }
}

// ---------- kernel 2/3: tiled GEMM + bias + relu (BM=BN=128, BK=16, 8x8 thread tile) ----------
__global__ __launch_bounds__(256)
void gemm_bias_relu(const float* __restrict__ A, const float* __restrict__ W,
                    const float* __restrict__ bias, float* __restrict__ C,
                    int M, int K, int N)
{
    __shared__ __align__(16) float As[16][128];
    __shared__ __align__(16) float Bs[16][128];
    const int t = threadIdx.x;
    const int m0 = blockIdx.y * 128, n0 = blockIdx.x * 128;
    // square warp footprint: 8 m-groups x 4 n-groups per warp
    const int lane = t & 31, wrp = t >> 5;
    const int tm = (lane & 7) | ((wrp & 1) << 3);
    const int tn = (lane >> 3) | ((wrp >> 1) << 2);

    ULL acc[8][4];
    #pragma unroll
    for (int m = 0; m < 8; m++)
        #pragma unroll
        for (int p = 0; p < 4; p++) acc[m][p] = 0ull;

    for (int k0 = 0; k0 < K; k0 += 16) {
        __syncthreads();
        #pragma unroll
        for (int q = 0; q < 2; q++) {
            int f = t + q * 256;
            int row = f >> 2, kq = (f & 3) * 4;
            int rg = m0 + row; if (rg >= M) rg = M - 1;
            float4 v = *(const float4*)(A + (size_t)rg * K + k0 + kq);
            As[kq + 0][row] = v.x; As[kq + 1][row] = v.y;
            As[kq + 2][row] = v.z; As[kq + 3][row] = v.w;
        }
        #pragma unroll
        for (int q = 0; q < 2; q++) {
            int f = t + q * 256;
            int r = f >> 5, nc = (f & 31) * 4;
            *(float4*)&Bs[r][nc] = *(const float4*)(W + (size_t)(k0 + r) * N + n0 + nc);
        }
        __syncthreads();
        #pragma unroll
        for (int k = 0; k < 16; k++) {
            float4 a0 = *(const float4*)&As[k][tm * 8];
            float4 a1 = *(const float4*)&As[k][tm * 8 + 4];
            const ulonglong2* bp = (const ulonglong2*)&Bs[k][tn * 8];
            ulonglong2 bA = bp[0], bB = bp[1];
            ULL am[8];
            am[0] = dup2(a0.x); am[1] = dup2(a0.y); am[2] = dup2(a0.z); am[3] = dup2(a0.w);
            am[4] = dup2(a1.x); am[5] = dup2(a1.y); am[6] = dup2(a1.z); am[7] = dup2(a1.w);
            #pragma unroll
            for (int m = 0; m < 8; m++) {
                acc[m][0] = fma2(am[m], bA.x, acc[m][0]);
                acc[m][1] = fma2(am[m], bA.y, acc[m][1]);
                acc[m][2] = fma2(am[m], bB.x, acc[m][2]);
                acc[m][3] = fma2(am[m], bB.y, acc[m][3]);
            }
        }
    }
    float bn[8];
    #pragma unroll
    for (int p = 0; p < 8; p++) bn[p] = bias[n0 + tn * 8 + p];
    #pragma unroll
    for (int m = 0; m < 8; m++) {
        int row = m0 + tm * 8 + m;
        if (row < M) {
            float* crow = C + (size_t)row * N + n0 + tn * 8;
            #pragma unroll
            for (int p = 0; p < 4; p++) {
                float v0, v1; unpack2(acc[m][p], v0, v1);
                crow[2 * p]     = fmaxf(v0 + bn[2 * p], 0.f);
                crow[2 * p + 1] = fmaxf(v1 + bn[2 * p + 1], 0.f);
            }
        }
    }
}

// ---------- kernel 4: heads (reg/score projections, class gather, box decode) ----------
__global__ __launch_bounds__(128)
void heads_kernel(const float* __restrict__ bboxes, const int* __restrict__ cls,
                  const float* __restrict__ reg_w, const float* __restrict__ reg_b,
                  const float* __restrict__ score_w, const float* __restrict__ score_b,
                  float* __restrict__ out, int N)
{
    __shared__ float h[512];
    __shared__ float ob[16];
    const int box = blockIdx.x;
    const int t = threadIdx.x;
    const float* hrow = g_h2 + (size_t)box * 512;
    *(float4*)&h[t * 4] = *(const float4*)&hrow[t * 4];
    __syncthreads();

    const int w = t >> 5, l = t & 31;
    #pragma unroll
    for (int r = 0; r < 4; r++) {
        int o = w + r * 4;
        if (o < 15) {
            float s = 0.f;
            if (o < 12) {
                for (int k = l; k < 512; k += 32) s += h[k] * reg_w[k * 12 + o];
            } else {
                int oc = o - 12;
                for (int k = l; k < 512; k += 32) s += h[k] * score_w[k * 3 + oc];
            }
            #pragma unroll
            for (int d = 16; d; d >>= 1) s += __shfl_xor_sync(0xffffffffu, s, d);
            if (l == 0) ob[o] = s + (o < 12 ? reg_b[o] : score_b[o - 12]);
        }
    }
    __syncthreads();
    if (t == 0) {
        int c = cls[box];
        float d0 = ob[c * 4 + 0], d1 = ob[c * 4 + 1];
        float d2 = ob[c * 4 + 2], d3 = ob[c * 4 + 3];
        float sc = ob[12 + c];
        float y1 = bboxes[box * 4 + 0], x1 = bboxes[box * 4 + 1];
        float y2 = bboxes[box * 4 + 2], x2 = bboxes[box * 4 + 3];
        float hh = y2 - y1, ww = x2 - x1;
        float cy = y1 + 0.5f * hh + d0 * hh;
        float cx = x1 + 0.5f * ww + d1 * ww;
        float nh = hh * expf(d2);
        float nw = ww * expf(d3);
        out[box] = sc;                       // regression_scores [N,1]
        float* rg = out + N;                 // regressions [N,4]
        rg[box * 4 + 0] = d0; rg[box * 4 + 1] = d1;
        rg[box * 4 + 2] = d2; rg[box * 4 + 3] = d3;
        float* bb = out + (size_t)N * 5;     // regression_bboxes [N,4]
        bb[box * 4 + 0] = cy - 0.5f * nh;
        bb[box * 4 + 1] = cx - 0.5f * nw;
        bb[box * 4 + 2] = cy + 0.5f * nh;
        bb[box * 4 + 3] = cx + 0.5f * nw;
    }
}

// ---------- host launcher ----------
extern "C" void kernel_launch(void* const* d_in, const int* in_sizes, int n_in,
                              void* d_out, int out_size)
{
    const float* features = (const float*)d_in[0];
    const float* proposal = (const float*)d_in[1];
    const float* bboxes   = (const float*)d_in[2];
    const int*   box_idx  = (const int*)d_in[3];
    const int*   cls      = (const int*)d_in[4];
    const float* c1w = (const float*)d_in[5];
    const float* c1b = (const float*)d_in[6];
    const float* c2w = (const float*)d_in[7];
    const float* c2b = (const float*)d_in[8];
    const float* d1w = (const float*)d_in[9];
    const float* d1b = (const float*)d_in[10];
    const float* d2w = (const float*)d_in[11];
    const float* d2b = (const float*)d_in[12];
    const float* rgw = (const float*)d_in[13];
    const float* rgb = (const float*)d_in[14];
    const float* scw = (const float*)d_in[15];
    const float* scb = (const float*)d_in[16];
    float* out = (float*)d_out;

    const int N = in_sizes[2] / 4;  // number of boxes

    void *p_c2 = nullptr, *p_h1 = nullptr, *p_h2 = nullptr;
    cudaGetSymbolAddress(&p_c2, g_c2);
    cudaGetSymbolAddress(&p_h1, g_h1);
    cudaGetSymbolAddress(&p_h2, g_h2);

    cudaFuncSetAttribute(crop_conv_kernel,
                         cudaFuncAttributeMaxDynamicSharedMemorySize, SMEM_BYTES);

    crop_conv_kernel<<<N, CC_THREADS, SMEM_BYTES>>>(features, proposal, bboxes, box_idx,
                                                    c1w, c1b, c2w, c2b);

    dim3 g1(512 / 128, (N + 127) / 128);
    gemm_bias_relu<<<g1, 256>>>((const float*)p_c2, d1w, d1b, (float*)p_h1,
                                N, 2048, 512);

    dim3 g2(512 / 128, (N + 127) / 128);
    gemm_bias_relu<<<g2, 256>>>((const float*)p_h1, d2w, d2b, (float*)p_h2,
                                N, 512, 512);

    heads_kernel<<<N, 128>>>(bboxes, cls, rgw, rgb, scw, scb, out, N);
}

// round 16
// speedup vs baseline: 1.0856x; 1.0856x over previous
#include <cuda_runtime.h>
#include <math.h>

typedef unsigned long long ULL;

// ---------- packed f32x2 helpers (double-rate fp32 FMA path on sm_103a) ----------
__device__ __forceinline__ ULL fma2(ULL a, ULL b, ULL c) {
    ULL d;
    asm("fma.rn.f32x2 %0, %1, %2, %3;" : "=l"(d) : "l"(a), "l"(b), "l"(c));
    return d;
}
__device__ __forceinline__ ULL pack2(float lo, float hi) {
    ULL r;
    asm("mov.b64 %0, {%1, %2};" : "=l"(r) : "f"(lo), "f"(hi));
    return r;
}
__device__ __forceinline__ ULL dup2(float v) { return pack2(v, v); }
__device__ __forceinline__ void unpack2(ULL v, float& lo, float& hi) {
    asm("mov.b64 {%0, %1}, %2;" : "=f"(lo), "=f"(hi) : "l"(v));
}

// ---------- cp.async helpers ----------
__device__ __forceinline__ void cp16(float* dst_sm, const float* src_g) {
    unsigned d = (unsigned)__cvta_generic_to_shared(dst_sm);
    asm volatile("cp.async.cg.shared.global [%0], [%1], 16;" :: "r"(d), "l"(src_g) : "memory");
}
__device__ __forceinline__ void cp_commit() {
    asm volatile("cp.async.commit_group;" ::: "memory");
}
template<int N> __device__ __forceinline__ void cp_wait() {
    asm volatile("cp.async.wait_group %0;" :: "n"(N) : "memory");
}

// ---------- global scratch (no allocation allowed) ----------
#define NBOX 4096
__device__ float g_c2[NBOX * 2048];   // conv2 output, flattened per box
__device__ float g_h1[NBOX * 512];    // dense1 output
__device__ float g_h2[NBOX * 512];    // dense2 output

// ---------- kernel 1: fused crop_and_resize + conv1 + conv2 (one block per box) ----------
// 256 threads/block (R14 config — best measured). smem layout (floats),
// pixel strides PADDED to break bank congruence:
//   crop: 17x17 pixels, stride 68  (19652 floats); reused as conv2 weight buf0 (16384)
//   c1:   9x9 pixels,  stride 132 (10692 floats); reused as conv2 partial buffer (4x2048)
//   w1:   conv1 weight double buffer (2 x 8192);   reused as conv2 weight buf1 (16384)
//   pix:  per-pixel crop params (256 x 8)
#define CROP_STRIDE 68
#define C1_STRIDE   132
#define CROP_OFF 0
#define C1_OFF   19652
#define W1_OFF   30344
#define PIX_OFF  46728
#define SMEM_FLOATS 48776
#define SMEM_BYTES  (SMEM_FLOATS * 4)

__global__ __launch_bounds__(256, 1)
void crop_conv_kernel(const float* __restrict__ features,
                      const float* __restrict__ proposal,
                      const float* __restrict__ bboxes,
                      const int*   __restrict__ box_idx,
                      const float* __restrict__ c1w,
                      const float* __restrict__ c1b,
                      const float* __restrict__ c2w,
                      const float* __restrict__ c2b)
{
    extern __shared__ float sm[];
    const int box = blockIdx.x;
    const int t   = threadIdx.x;

    // ---- prologue: prefetch conv1 weight slice 0 (hidden behind crop gather) ----
    {
        float* dst = sm + W1_OFF;
        #pragma unroll
        for (int q = 0; q < 8; q++) { int f = t + q * 256; cp16(dst + f * 4, c1w + f * 4); }
        cp_commit();
    }

    const float by1 = bboxes[box * 4 + 0];
    const float bx1 = bboxes[box * 4 + 1];
    const float by2 = bboxes[box * 4 + 2];
    const float bx2 = bboxes[box * 4 + 3];
    const int   bimg = box_idx[box];

    // ---- Phase 0: zero ONLY padding cells; compute per-pixel sample params ----
    {
        // crop row 16 (17 pixels): 17*68 = 1156 floats, contiguous at pixel 272
        for (int i = t; i < 1156; i += 256) sm[CROP_OFF + 272 * CROP_STRIDE + i] = 0.f;
        // crop col 16, rows 0..15: 16*68 = 1088 floats
        for (int i = t; i < 1088; i += 256) {
            int gy = i / CROP_STRIDE, j = i - gy * CROP_STRIDE;
            sm[CROP_OFF + (gy * 17 + 16) * CROP_STRIDE + j] = 0.f;
        }
        // c1 row 8 (9 pixels): 9*132 = 1188 floats, contiguous at pixel 72
        for (int i = t; i < 1188; i += 256) sm[C1_OFF + 72 * C1_STRIDE + i] = 0.f;
        // c1 col 8, rows 0..7: 8*132 = 1056 floats
        for (int i = t; i < 1056; i += 256) {
            int gy = i / C1_STRIDE, j = i - gy * C1_STRIDE;
            sm[C1_OFF + (gy * 9 + 8) * C1_STRIDE + j] = 0.f;
        }
    }
    {
        const int gy = t >> 4, gx = t & 15;
        float fy = (by1 + (gy * (1.0f / 15.0f)) * (by2 - by1)) * 511.0f;
        float fx = (bx1 + (gx * (1.0f / 15.0f)) * (bx2 - bx1)) * 511.0f;
        float fy0 = floorf(fy), fx0 = floorf(fx);
        float wy = fy - fy0, wx = fx - fx0;
        int iy0 = min(max((int)fy0, 0), 511); int iy1 = min(iy0 + 1, 511);
        int ix0 = min(max((int)fx0, 0), 511); int ix1 = min(ix0 + 1, 511);
        const float* pr = proposal + (size_t)bimg * 512 * 512;
        float p00 = pr[iy0 * 512 + ix0], p01 = pr[iy0 * 512 + ix1];
        float p10 = pr[iy1 * 512 + ix0], p11 = pr[iy1 * 512 + ix1];
        float ptop = p00 + wx * (p01 - p00);
        float pbot = p10 + wx * (p11 - p10);
        float pv = ptop + wy * (pbot - ptop);
        float* px = sm + PIX_OFF + t * 8;
        px[0] = __int_as_float(iy0); px[1] = __int_as_float(iy1);
        px[2] = __int_as_float(ix0); px[3] = __int_as_float(ix1);
        px[4] = wy; px[5] = wx; px[6] = pv;
    }
    __syncthreads();

    // ---- Phase 1: gather features (coalesced: 16 lanes span the 64 channels) ----
    {
        const int c = (t & 15) * 4;
        const float* fbase = features + (size_t)bimg * 512 * 512 * 64 + c;
        #pragma unroll 4
        for (int pass = 0; pass < 16; pass++) {
            int p = pass * 16 + (t >> 4);
            const float* px = sm + PIX_OFF + p * 8;
            int iy0 = __float_as_int(px[0]), iy1 = __float_as_int(px[1]);
            int ix0 = __float_as_int(px[2]), ix1 = __float_as_int(px[3]);
            float wy = px[4], wx = px[5], pv = px[6];
            float4 v00 = *(const float4*)(fbase + ((size_t)iy0 * 512 + ix0) * 64);
            float4 v01 = *(const float4*)(fbase + ((size_t)iy0 * 512 + ix1) * 64);
            float4 v10 = *(const float4*)(fbase + ((size_t)iy1 * 512 + ix0) * 64);
            float4 v11 = *(const float4*)(fbase + ((size_t)iy1 * 512 + ix1) * 64);
            float4 r;
            {
                float tp, bt;
                tp = v00.x + wx * (v01.x - v00.x); bt = v10.x + wx * (v11.x - v10.x);
                r.x = (tp + wy * (bt - tp)) * pv;
                tp = v00.y + wx * (v01.y - v00.y); bt = v10.y + wx * (v11.y - v10.y);
                r.y = (tp + wy * (bt - tp)) * pv;
                tp = v00.z + wx * (v01.z - v00.z); bt = v10.z + wx * (v11.z - v10.z);
                r.z = (tp + wy * (bt - tp)) * pv;
                tp = v00.w + wx * (v01.w - v00.w); bt = v10.w + wx * (v11.w - v10.w);
                r.w = (tp + wy * (bt - tp)) * pv;
            }
            int gy = p >> 4, gx = p & 15;
            *(float4*)(sm + CROP_OFF + (gy * 17 + gx) * CROP_STRIDE + c) = r;
        }
    }

    // ---- Phase 2: conv1 (stride 2, SAME pad bottom/right) as 9 smem GEMMs.
    //      Warp footprint: 8 px-groups x 4 co-groups -> 1-phase weight LDS.
    //      Single-sync pipeline: wait -> sync -> prefetch(s+1) -> compute(s). ----
    const int lane = t & 31, wrp = t >> 5;
    const int pxg = (lane & 7) | ((wrp & 1) << 3);    // 0..15 (4 pixels each)
    const int cog = (lane >> 3) | ((wrp >> 1) << 2);  // 0..15 (8 channels each)
    const int co0 = cog * 8;
    int oyv[4], oxv[4];
    #pragma unroll
    for (int i = 0; i < 4; i++) { int p = pxg * 4 + i; oyv[i] = p >> 3; oxv[i] = p & 7; }

    ULL acc[4][4];
    #pragma unroll
    for (int jp = 0; jp < 4; jp++) {
        ULL bb = pack2(c1b[co0 + 2 * jp], c1b[co0 + 2 * jp + 1]);
        #pragma unroll
        for (int i = 0; i < 4; i++) acc[i][jp] = bb;
    }

    #define CONV1_STEP(u, comp)                                                   \
        {                                                                         \
            const ulonglong2* wp = (const ulonglong2*)(wb + (ci4 + u) * 128 + co0);\
            ulonglong2 w01 = wp[0];                                               \
            ulonglong2 w23 = wp[1];                                               \
            _Pragma("unroll")                                                     \
            for (int i = 0; i < 4; i++) {                                         \
                ULL a2 = dup2(av[i].comp);                                        \
                acc[i][0] = fma2(a2, w01.x, acc[i][0]);                           \
                acc[i][1] = fma2(a2, w01.y, acc[i][1]);                           \
                acc[i][2] = fma2(a2, w23.x, acc[i][2]);                           \
                acc[i][3] = fma2(a2, w23.y, acc[i][3]);                           \
            }                                                                     \
        }

    for (int s = 0; s < 9; s++) {
        cp_wait<0>();        // weight slice s copies (mine) complete
        __syncthreads();     // everyone's copies visible; compute s-1 fully done
        if (s < 8) {         // prefetch s+1 into the buffer compute s-1 just freed
            const float* src = c1w + (s + 1) * 8192;
            float* dst = sm + W1_OFF + ((s + 1) & 1) * 8192;
            #pragma unroll
            for (int q = 0; q < 8; q++) { int f = t + q * 256; cp16(dst + f * 4, src + f * 4); }
            cp_commit();
        }

        const float* wb = sm + W1_OFF + (s & 1) * 8192;
        const int ky = s / 3, kx = s - 3 * (s / 3);
        int pb[4];
        #pragma unroll
        for (int i = 0; i < 4; i++)
            pb[i] = ((oyv[i] * 2 + ky) * 17 + (oxv[i] * 2 + kx)) * CROP_STRIDE;
        #pragma unroll 4
        for (int ci4 = 0; ci4 < 64; ci4 += 4) {
            float4 av[4];
            #pragma unroll
            for (int i = 0; i < 4; i++)
                av[i] = *(const float4*)(sm + CROP_OFF + pb[i] + ci4);
            CONV1_STEP(0, x)
            CONV1_STEP(1, y)
            CONV1_STEP(2, z)
            CONV1_STEP(3, w)
        }
    }
    // relu + store into zero-padded 9x9 (stride 132) c1 (writes C1, no CROP hazard)
    #pragma unroll
    for (int i = 0; i < 4; i++) {
        float* dst = sm + C1_OFF + (oyv[i] * 9 + oxv[i]) * C1_STRIDE + co0;
        #pragma unroll
        for (int jp = 0; jp < 4; jp++) {
            float v0, v1; unpack2(acc[i][jp], v0, v1);
            dst[2 * jp]     = fmaxf(v0, 0.f);
            dst[2 * jp + 1] = fmaxf(v1, 0.f);
        }
    }
    __syncthreads();   // all conv1 CROP reads + c1 stores done

    // ---- Phase 3: conv2 as 9 smem GEMMs, 4-way K-split, double-buffered weights ----
    // prefetch conv2 slice 0 into crop region (now dead)
    {
        float* dst = sm + CROP_OFF;
        #pragma unroll
        for (int q = 0; q < 16; q++) { int f = t + q * 256; cp16(dst + f * 4, c2w + f * 4); }
        cp_commit();
    }

    const int ks  = t >> 6;           // K-split 0..3
    const int rem = t & 63;
    const int pg2 = rem & 3;          // 4 pixel groups  -> broadcast a-loads
    const int cg2 = rem >> 2;         // 16 co groups (8 per warp)
    const int co2 = cg2 * 8;
    int oy2[4], ox2[4];
    #pragma unroll
    for (int i = 0; i < 4; i++) { int p = pg2 * 4 + i; oy2[i] = p >> 2; ox2[i] = p & 3; }

    ULL ac2[4][4];
    #pragma unroll
    for (int i = 0; i < 4; i++)
        #pragma unroll
        for (int jp = 0; jp < 4; jp++) ac2[i][jp] = 0ull;

    #define CONV2_STEP(u, comp)                                                   \
        {                                                                         \
            const ulonglong2* wp = (const ulonglong2*)(wb + (ciw + u) * 128 + co2);\
            ulonglong2 w01 = wp[0];                                               \
            ulonglong2 w23 = wp[1];                                               \
            _Pragma("unroll")                                                     \
            for (int i = 0; i < 4; i++) {                                         \
                ULL a2 = dup2(av[i].comp);                                        \
                ac2[i][0] = fma2(a2, w01.x, ac2[i][0]);                           \
                ac2[i][1] = fma2(a2, w01.y, ac2[i][1]);                           \
                ac2[i][2] = fma2(a2, w23.x, ac2[i][2]);                           \
                ac2[i][3] = fma2(a2, w23.y, ac2[i][3]);                           \
            }                                                                     \
        }

    const int cibeg = ks * 32;
    for (int s = 0; s < 9; s++) {
        cp_wait<0>();
        __syncthreads();
        if (s < 8) {
            const float* src = c2w + (s + 1) * 16384;
            float* dst = sm + (((s + 1) & 1) ? W1_OFF : CROP_OFF);
            #pragma unroll
            for (int q = 0; q < 16; q++) { int f = t + q * 256; cp16(dst + f * 4, src + f * 4); }
            cp_commit();
        }

        const float* wb = sm + ((s & 1) ? W1_OFF : CROP_OFF);
        const int ky = s / 3, kx = s - 3 * (s / 3);
        int pb[4];
        #pragma unroll
        for (int i = 0; i < 4; i++)
            pb[i] = ((oy2[i] * 2 + ky) * 9 + (ox2[i] * 2 + kx)) * C1_STRIDE + cibeg;
        #pragma unroll 2
        for (int ci4 = 0; ci4 < 32; ci4 += 4) {
            float4 av[4];
            #pragma unroll
            for (int i = 0; i < 4; i++)
                av[i] = *(const float4*)(sm + C1_OFF + pb[i] + ci4);
            const int ciw = cibeg + ci4;   // absolute weight row
            CONV2_STEP(0, x)
            CONV2_STEP(1, y)
            CONV2_STEP(2, z)
            CONV2_STEP(3, w)
        }
    }
    __syncthreads();   // all conv2 C1 reads done before partial writes reuse C1
    // write K-split partials into the (now dead) c1 region: 4 x 2048
    #pragma unroll
    for (int i = 0; i < 4; i++) {
        int px = pg2 * 4 + i;
        float* dst = sm + C1_OFF + ks * 2048 + px * 128 + co2;
        #pragma unroll
        for (int jp = 0; jp < 4; jp++) {
            float v0, v1; unpack2(ac2[i][jp], v0, v1);
            dst[2 * jp] = v0; dst[2 * jp + 1] = v1;
        }
    }
    __syncthreads();
    {   // reduce + bias + relu -> flattened conv2 output in global
        float* c2out = g_c2 + (size_t)box * 2048;
        #pragma unroll
        for (int r = 0; r < 8; r++) {
            int o = t * 8 + r;
            float v = sm[C1_OFF + o] + sm[C1_OFF + 2048 + o]
                    + sm[C1_OFF + 4096 + o] + sm[C1_OFF + 6144 + o] + c2b[o & 127];
            c2out[o] = fmaxf(v, 0.f);
        }
    }
}

// ---------- kernel 2/3: tiled GEMM + bias + relu (BM=BN=128, BK=16, 8x8 thread tile) ----------
__global__ __launch_bounds__(256)
void gemm_bias_relu(const float* __restrict__ A, const float* __restrict__ W,
                    const float* __restrict__ bias, float* __restrict__ C,
                    int M, int K, int N)
{
    __shared__ __align__(16) float As[16][128];
    __shared__ __align__(16) float Bs[16][128];
    const int t = threadIdx.x;
    const int m0 = blockIdx.y * 128, n0 = blockIdx.x * 128;
    // square warp footprint: 8 m-groups x 4 n-groups per warp
    const int lane = t & 31, wrp = t >> 5;
    const int tm = (lane & 7) | ((wrp & 1) << 3);
    const int tn = (lane >> 3) | ((wrp >> 1) << 2);

    ULL acc[8][4];
    #pragma unroll
    for (int m = 0; m < 8; m++)
        #pragma unroll
        for (int p = 0; p < 4; p++) acc[m][p] = 0ull;

    for (int k0 = 0; k0 < K; k0 += 16) {
        __syncthreads();
        #pragma unroll
        for (int q = 0; q < 2; q++) {
            int f = t + q * 256;
            int row = f >> 2, kq = (f & 3) * 4;
            int rg = m0 + row; if (rg >= M) rg = M - 1;
            float4 v = *(const float4*)(A + (size_t)rg * K + k0 + kq);
            As[kq + 0][row] = v.x; As[kq + 1][row] = v.y;
            As[kq + 2][row] = v.z; As[kq + 3][row] = v.w;
        }
        #pragma unroll
        for (int q = 0; q < 2; q++) {
            int f = t + q * 256;
            int r = f >> 5, nc = (f & 31) * 4;
            *(float4*)&Bs[r][nc] = *(const float4*)(W + (size_t)(k0 + r) * N + n0 + nc);
        }
        __syncthreads();
        #pragma unroll
        for (int k = 0; k < 16; k++) {
            float4 a0 = *(const float4*)&As[k][tm * 8];
            float4 a1 = *(const float4*)&As[k][tm * 8 + 4];
            const ulonglong2* bp = (const ulonglong2*)&Bs[k][tn * 8];
            ulonglong2 bA = bp[0], bB = bp[1];
            ULL am[8];
            am[0] = dup2(a0.x); am[1] = dup2(a0.y); am[2] = dup2(a0.z); am[3] = dup2(a0.w);
            am[4] = dup2(a1.x); am[5] = dup2(a1.y); am[6] = dup2(a1.z); am[7] = dup2(a1.w);
            #pragma unroll
            for (int m = 0; m < 8; m++) {
                acc[m][0] = fma2(am[m], bA.x, acc[m][0]);
                acc[m][1] = fma2(am[m], bA.y, acc[m][1]);
                acc[m][2] = fma2(am[m], bB.x, acc[m][2]);
                acc[m][3] = fma2(am[m], bB.y, acc[m][3]);
            }
        }
    }
    float bn[8];
    #pragma unroll
    for (int p = 0; p < 8; p++) bn[p] = bias[n0 + tn * 8 + p];
    #pragma unroll
    for (int m = 0; m < 8; m++) {
        int row = m0 + tm * 8 + m;
        if (row < M) {
            float* crow = C + (size_t)row * N + n0 + tn * 8;
            #pragma unroll
            for (int p = 0; p < 4; p++) {
                float v0, v1; unpack2(acc[m][p], v0, v1);
                crow[2 * p]     = fmaxf(v0 + bn[2 * p], 0.f);
                crow[2 * p + 1] = fmaxf(v1 + bn[2 * p + 1], 0.f);
            }
        }
    }
}

// ---------- kernel 4: heads (reg/score projections, class gather, box decode) ----------
__global__ __launch_bounds__(128)
void heads_kernel(const float* __restrict__ bboxes, const int* __restrict__ cls,
                  const float* __restrict__ reg_w, const float* __restrict__ reg_b,
                  const float* __restrict__ score_w, const float* __restrict__ score_b,
                  float* __restrict__ out, int N)
{
    __shared__ float h[512];
    __shared__ float ob[16];
    const int box = blockIdx.x;
    const int t = threadIdx.x;
    const float* hrow = g_h2 + (size_t)box * 512;
    *(float4*)&h[t * 4] = *(const float4*)&hrow[t * 4];
    __syncthreads();

    const int w = t >> 5, l = t & 31;
    #pragma unroll
    for (int r = 0; r < 4; r++) {
        int o = w + r * 4;
        if (o < 15) {
            float s = 0.f;
            if (o < 12) {
                for (int k = l; k < 512; k += 32) s += h[k] * reg_w[k * 12 + o];
            } else {
                int oc = o - 12;
                for (int k = l; k < 512; k += 32) s += h[k] * score_w[k * 3 + oc];
            }
            #pragma unroll
            for (int d = 16; d; d >>= 1) s += __shfl_xor_sync(0xffffffffu, s, d);
            if (l == 0) ob[o] = s + (o < 12 ? reg_b[o] : score_b[o - 12]);
        }
    }
    __syncthreads();
    if (t == 0) {
        int c = cls[box];
        float d0 = ob[c * 4 + 0], d1 = ob[c * 4 + 1];
        float d2 = ob[c * 4 + 2], d3 = ob[c * 4 + 3];
        float sc = ob[12 + c];
        float y1 = bboxes[box * 4 + 0], x1 = bboxes[box * 4 + 1];
        float y2 = bboxes[box * 4 + 2], x2 = bboxes[box * 4 + 3];
        float hh = y2 - y1, ww = x2 - x1;
        float cy = y1 + 0.5f * hh + d0 * hh;
        float cx = x1 + 0.5f * ww + d1 * ww;
        float nh = hh * expf(d2);
        float nw = ww * expf(d3);
        out[box] = sc;                       // regression_scores [N,1]
        float* rg = out + N;                 // regressions [N,4]
        rg[box * 4 + 0] = d0; rg[box * 4 + 1] = d1;
        rg[box * 4 + 2] = d2; rg[box * 4 + 3] = d3;
        float* bb = out + (size_t)N * 5;     // regression_bboxes [N,4]
        bb[box * 4 + 0] = cy - 0.5f * nh;
        bb[box * 4 + 1] = cx - 0.5f * nw;
        bb[box * 4 + 2] = cy + 0.5f * nh;
        bb[box * 4 + 3] = cx + 0.5f * nw;
    }
}

// ---------- host launcher ----------
extern "C" void kernel_launch(void* const* d_in, const int* in_sizes, int n_in,
                              void* d_out, int out_size)
{
    const float* features = (const float*)d_in[0];
    const float* proposal = (const float*)d_in[1];
    const float* bboxes   = (const float*)d_in[2];
    const int*   box_idx  = (const int*)d_in[3];
    const int*   cls      = (const int*)d_in[4];
    const float* c1w = (const float*)d_in[5];
    const float* c1b = (const float*)d_in[6];
    const float* c2w = (const float*)d_in[7];
    const float* c2b = (const float*)d_in[8];
    const float* d1w = (const float*)d_in[9];
    const float* d1b = (const float*)d_in[10];
    const float* d2w = (const float*)d_in[11];
    const float* d2b = (const float*)d_in[12];
    const float* rgw = (const float*)d_in[13];
    const float* rgb = (const float*)d_in[14];
    const float* scw = (const float*)d_in[15];
    const float* scb = (const float*)d_in[16];
    float* out = (float*)d_out;

    const int N = in_sizes[2] / 4;  // number of boxes

    void *p_c2 = nullptr, *p_h1 = nullptr, *p_h2 = nullptr;
    cudaGetSymbolAddress(&p_c2, g_c2);
    cudaGetSymbolAddress(&p_h1, g_h1);
    cudaGetSymbolAddress(&p_h2, g_h2);

    cudaFuncSetAttribute(crop_conv_kernel,
                         cudaFuncAttributeMaxDynamicSharedMemorySize, SMEM_BYTES);

    crop_conv_kernel<<<N, 256, SMEM_BYTES>>>(features, proposal, bboxes, box_idx,
                                             c1w, c1b, c2w, c2b);

    dim3 g1(512 / 128, (N + 127) / 128);
    gemm_bias_relu<<<g1, 256>>>((const float*)p_c2, d1w, d1b, (float*)p_h1,
                                N, 2048, 512);

    dim3 g2(512 / 128, (N + 127) / 128);
    gemm_bias_relu<<<g2, 256>>>((const float*)p_h1, d2w, d2b, (float*)p_h2,
                                N, 512, 512);

    heads_kernel<<<N, 128>>>(bboxes, cls, rgw, rgb, scw, scb, out, N);
}

// round 17
// speedup vs baseline: 1.0951x; 1.0087x over previous
#include <cuda_runtime.h>
#include <math.h>

typedef unsigned long long ULL;

// ---------- packed f32x2 helpers (double-rate fp32 FMA path on sm_103a) ----------
__device__ __forceinline__ ULL fma2(ULL a, ULL b, ULL c) {
    ULL d;
    asm("fma.rn.f32x2 %0, %1, %2, %3;" : "=l"(d) : "l"(a), "l"(b), "l"(c));
    return d;
}
__device__ __forceinline__ ULL pack2(float lo, float hi) {
    ULL r;
    asm("mov.b64 %0, {%1, %2};" : "=l"(r) : "f"(lo), "f"(hi));
    return r;
}
__device__ __forceinline__ ULL dup2(float v) { return pack2(v, v); }
__device__ __forceinline__ void unpack2(ULL v, float& lo, float& hi) {
    asm("mov.b64 {%0, %1}, %2;" : "=f"(lo), "=f"(hi) : "l"(v));
}

// ---------- cp.async helpers ----------
__device__ __forceinline__ void cp16(float* dst_sm, const float* src_g) {
    unsigned d = (unsigned)__cvta_generic_to_shared(dst_sm);
    asm volatile("cp.async.cg.shared.global [%0], [%1], 16;" :: "r"(d), "l"(src_g) : "memory");
}
__device__ __forceinline__ void cp_commit() {
    asm volatile("cp.async.commit_group;" ::: "memory");
}
template<int N> __device__ __forceinline__ void cp_wait() {
    asm volatile("cp.async.wait_group %0;" :: "n"(N) : "memory");
}

// ---------- global scratch (no allocation allowed) ----------
#define NBOX 4096
__device__ float g_c2[NBOX * 2048];   // conv2 output, flattened per box
__device__ float g_h1[NBOX * 512];    // dense1 output
__device__ float g_h2[NBOX * 512];    // dense2 output

// ---------- kernel 1: fused crop_and_resize + conv1 + conv2 (one block per box) ----------
// 256 threads/block. smem layout (floats), pixel strides PADDED to break bank
// congruence:
//   crop: 17x17 pixels, stride 68  (19652 floats); reused as conv2 weight buf0 (16384)
//   c1:   9x9 pixels,  stride 132 (10692 floats); reused as conv2 partial buffer (4x2048)
//   w1:   conv1 weight double buffer (2 x 8192);   reused as conv2 weight buf1 (16384)
//   pix:  per-pixel crop params (256 x 8)
#define CROP_STRIDE 68
#define C1_STRIDE   132
#define CROP_OFF 0
#define C1_OFF   19652
#define W1_OFF   30344
#define PIX_OFF  46728
#define SMEM_FLOATS 48776
#define SMEM_BYTES  (SMEM_FLOATS * 4)

__global__ __launch_bounds__(256, 1)
void crop_conv_kernel(const float* __restrict__ features,
                      const float* __restrict__ proposal,
                      const float* __restrict__ bboxes,
                      const int*   __restrict__ box_idx,
                      const float* __restrict__ c1w,
                      const float* __restrict__ c1b,
                      const float* __restrict__ c2w,
                      const float* __restrict__ c2b)
{
    extern __shared__ float sm[];
    const int box = blockIdx.x;
    const int t   = threadIdx.x;

    // ---- prologue: prefetch conv1 weight slice 0 (hidden behind crop gather) ----
    {
        float* dst = sm + W1_OFF;
        #pragma unroll
        for (int q = 0; q < 8; q++) { int f = t + q * 256; cp16(dst + f * 4, c1w + f * 4); }
        cp_commit();
    }

    const float by1 = bboxes[box * 4 + 0];
    const float bx1 = bboxes[box * 4 + 1];
    const float by2 = bboxes[box * 4 + 2];
    const float bx2 = bboxes[box * 4 + 3];
    const int   bimg = box_idx[box];

    // ---- Phase 0: zero ONLY padding cells; compute per-pixel sample params ----
    {
        // crop row 16 (17 pixels): 17*68 = 1156 floats, contiguous at pixel 272
        for (int i = t; i < 1156; i += 256) sm[CROP_OFF + 272 * CROP_STRIDE + i] = 0.f;
        // crop col 16, rows 0..15: 16*68 = 1088 floats
        for (int i = t; i < 1088; i += 256) {
            int gy = i / CROP_STRIDE, j = i - gy * CROP_STRIDE;
            sm[CROP_OFF + (gy * 17 + 16) * CROP_STRIDE + j] = 0.f;
        }
        // c1 row 8 (9 pixels): 9*132 = 1188 floats, contiguous at pixel 72
        for (int i = t; i < 1188; i += 256) sm[C1_OFF + 72 * C1_STRIDE + i] = 0.f;
        // c1 col 8, rows 0..7: 8*132 = 1056 floats
        for (int i = t; i < 1056; i += 256) {
            int gy = i / C1_STRIDE, j = i - gy * C1_STRIDE;
            sm[C1_OFF + (gy * 9 + 8) * C1_STRIDE + j] = 0.f;
        }
    }
    {
        const int gy = t >> 4, gx = t & 15;
        float fy = (by1 + (gy * (1.0f / 15.0f)) * (by2 - by1)) * 511.0f;
        float fx = (bx1 + (gx * (1.0f / 15.0f)) * (bx2 - bx1)) * 511.0f;
        float fy0 = floorf(fy), fx0 = floorf(fx);
        float wy = fy - fy0, wx = fx - fx0;
        int iy0 = min(max((int)fy0, 0), 511); int iy1 = min(iy0 + 1, 511);
        int ix0 = min(max((int)fx0, 0), 511); int ix1 = min(ix0 + 1, 511);
        const float* pr = proposal + (size_t)bimg * 512 * 512;
        float p00 = pr[iy0 * 512 + ix0], p01 = pr[iy0 * 512 + ix1];
        float p10 = pr[iy1 * 512 + ix0], p11 = pr[iy1 * 512 + ix1];
        float ptop = p00 + wx * (p01 - p00);
        float pbot = p10 + wx * (p11 - p10);
        float pv = ptop + wy * (pbot - ptop);
        float* px = sm + PIX_OFF + t * 8;
        px[0] = __int_as_float(iy0); px[1] = __int_as_float(iy1);
        px[2] = __int_as_float(ix0); px[3] = __int_as_float(ix1);
        px[4] = wy; px[5] = wx; px[6] = pv;
    }
    __syncthreads();

    // ---- Phase 1: gather features (coalesced: 16 lanes span the 64 channels) ----
    {
        const int c = (t & 15) * 4;
        const float* fbase = features + (size_t)bimg * 512 * 512 * 64 + c;
        #pragma unroll 4
        for (int pass = 0; pass < 16; pass++) {
            int p = pass * 16 + (t >> 4);
            const float* px = sm + PIX_OFF + p * 8;
            int iy0 = __float_as_int(px[0]), iy1 = __float_as_int(px[1]);
            int ix0 = __float_as_int(px[2]), ix1 = __float_as_int(px[3]);
            float wy = px[4], wx = px[5], pv = px[6];
            float4 v00 = *(const float4*)(fbase + ((size_t)iy0 * 512 + ix0) * 64);
            float4 v01 = *(const float4*)(fbase + ((size_t)iy0 * 512 + ix1) * 64);
            float4 v10 = *(const float4*)(fbase + ((size_t)iy1 * 512 + ix0) * 64);
            float4 v11 = *(const float4*)(fbase + ((size_t)iy1 * 512 + ix1) * 64);
            float4 r;
            {
                float tp, bt;
                tp = v00.x + wx * (v01.x - v00.x); bt = v10.x + wx * (v11.x - v10.x);
                r.x = (tp + wy * (bt - tp)) * pv;
                tp = v00.y + wx * (v01.y - v00.y); bt = v10.y + wx * (v11.y - v10.y);
                r.y = (tp + wy * (bt - tp)) * pv;
                tp = v00.z + wx * (v01.z - v00.z); bt = v10.z + wx * (v11.z - v10.z);
                r.z = (tp + wy * (bt - tp)) * pv;
                tp = v00.w + wx * (v01.w - v00.w); bt = v10.w + wx * (v11.w - v10.w);
                r.w = (tp + wy * (bt - tp)) * pv;
            }
            int gy = p >> 4, gx = p & 15;
            *(float4*)(sm + CROP_OFF + (gy * 17 + gx) * CROP_STRIDE + c) = r;
        }
    }

    // ---- Phase 2: conv1 (stride 2, SAME pad bottom/right) as 9 smem GEMMs.
    //      Warp footprint: 8 px-groups x 4 co-groups -> 1-phase weight LDS.
    //      Single-sync pipeline: wait -> sync -> prefetch(s+1) -> compute(s). ----
    const int lane = t & 31, wrp = t >> 5;
    const int pxg = (lane & 7) | ((wrp & 1) << 3);    // 0..15 (4 pixels each)
    const int cog = (lane >> 3) | ((wrp >> 1) << 2);  // 0..15 (8 channels each)
    const int co0 = cog * 8;
    int oyv[4], oxv[4];
    #pragma unroll
    for (int i = 0; i < 4; i++) { int p = pxg * 4 + i; oyv[i] = p >> 3; oxv[i] = p & 7; }

    ULL acc[4][4];
    #pragma unroll
    for (int jp = 0; jp < 4; jp++) {
        ULL bb = pack2(c1b[co0 + 2 * jp], c1b[co0 + 2 * jp + 1]);
        #pragma unroll
        for (int i = 0; i < 4; i++) acc[i][jp] = bb;
    }

    #define CONV1_STEP(u, comp)                                                   \
        {                                                                         \
            const ulonglong2* wp = (const ulonglong2*)(wb + (ci4 + u) * 128 + co0);\
            ulonglong2 w01 = wp[0];                                               \
            ulonglong2 w23 = wp[1];                                               \
            _Pragma("unroll")                                                     \
            for (int i = 0; i < 4; i++) {                                         \
                ULL a2 = dup2(av[i].comp);                                        \
                acc[i][0] = fma2(a2, w01.x, acc[i][0]);                           \
                acc[i][1] = fma2(a2, w01.y, acc[i][1]);                           \
                acc[i][2] = fma2(a2, w23.x, acc[i][2]);                           \
                acc[i][3] = fma2(a2, w23.y, acc[i][3]);                           \
            }                                                                     \
        }

    for (int s = 0; s < 9; s++) {
        cp_wait<0>();        // weight slice s copies (mine) complete
        __syncthreads();     // everyone's copies visible; compute s-1 fully done
        if (s < 8) {         // prefetch s+1 into the buffer compute s-1 just freed
            const float* src = c1w + (s + 1) * 8192;
            float* dst = sm + W1_OFF + ((s + 1) & 1) * 8192;
            #pragma unroll
            for (int q = 0; q < 8; q++) { int f = t + q * 256; cp16(dst + f * 4, src + f * 4); }
            cp_commit();
        }

        const float* wb = sm + W1_OFF + (s & 1) * 8192;
        const int ky = s / 3, kx = s - 3 * (s / 3);
        int pb[4];
        #pragma unroll
        for (int i = 0; i < 4; i++)
            pb[i] = ((oyv[i] * 2 + ky) * 17 + (oxv[i] * 2 + kx)) * CROP_STRIDE;
        #pragma unroll 4
        for (int ci4 = 0; ci4 < 64; ci4 += 4) {
            float4 av[4];
            #pragma unroll
            for (int i = 0; i < 4; i++)
                av[i] = *(const float4*)(sm + CROP_OFF + pb[i] + ci4);
            CONV1_STEP(0, x)
            CONV1_STEP(1, y)
            CONV1_STEP(2, z)
            CONV1_STEP(3, w)
        }
    }
    // relu + store into zero-padded 9x9 (stride 132) c1 (writes C1, no CROP hazard)
    #pragma unroll
    for (int i = 0; i < 4; i++) {
        float* dst = sm + C1_OFF + (oyv[i] * 9 + oxv[i]) * C1_STRIDE + co0;
        #pragma unroll
        for (int jp = 0; jp < 4; jp++) {
            float v0, v1; unpack2(acc[i][jp], v0, v1);
            dst[2 * jp]     = fmaxf(v0, 0.f);
            dst[2 * jp + 1] = fmaxf(v1, 0.f);
        }
    }
    __syncthreads();   // all conv1 CROP reads + c1 stores done

    // ---- Phase 3: conv2 as 9 smem GEMMs, 4-way K-split, double-buffered weights ----
    // prefetch conv2 slice 0 into crop region (now dead)
    {
        float* dst = sm + CROP_OFF;
        #pragma unroll
        for (int q = 0; q < 16; q++) { int f = t + q * 256; cp16(dst + f * 4, c2w + f * 4); }
        cp_commit();
    }

    const int ks  = t >> 6;           // K-split 0..3
    const int rem = t & 63;
    const int pg2 = rem & 3;          // 4 pixel groups  -> broadcast a-loads
    const int cg2 = rem >> 2;         // 16 co groups (8 per warp)
    const int co2 = cg2 * 8;
    int oy2[4], ox2[4];
    #pragma unroll
    for (int i = 0; i < 4; i++) { int p = pg2 * 4 + i; oy2[i] = p >> 2; ox2[i] = p & 3; }

    ULL ac2[4][4];
    #pragma unroll
    for (int i = 0; i < 4; i++)
        #pragma unroll
        for (int jp = 0; jp < 4; jp++) ac2[i][jp] = 0ull;

    #define CONV2_STEP(u, comp)                                                   \
        {                                                                         \
            const ulonglong2* wp = (const ulonglong2*)(wb + (ciw + u) * 128 + co2);\
            ulonglong2 w01 = wp[0];                                               \
            ulonglong2 w23 = wp[1];                                               \
            _Pragma("unroll")                                                     \
            for (int i = 0; i < 4; i++) {                                         \
                ULL a2 = dup2(av[i].comp);                                        \
                ac2[i][0] = fma2(a2, w01.x, ac2[i][0]);                           \
                ac2[i][1] = fma2(a2, w01.y, ac2[i][1]);                           \
                ac2[i][2] = fma2(a2, w23.x, ac2[i][2]);                           \
                ac2[i][3] = fma2(a2, w23.y, ac2[i][3]);                           \
            }                                                                     \
        }

    const int cibeg = ks * 32;
    for (int s = 0; s < 9; s++) {
        cp_wait<0>();
        __syncthreads();
        if (s < 8) {
            const float* src = c2w + (s + 1) * 16384;
            float* dst = sm + (((s + 1) & 1) ? W1_OFF : CROP_OFF);
            #pragma unroll
            for (int q = 0; q < 16; q++) { int f = t + q * 256; cp16(dst + f * 4, src + f * 4); }
            cp_commit();
        }

        const float* wb = sm + ((s & 1) ? W1_OFF : CROP_OFF);
        const int ky = s / 3, kx = s - 3 * (s / 3);
        int pb[4];
        #pragma unroll
        for (int i = 0; i < 4; i++)
            pb[i] = ((oy2[i] * 2 + ky) * 9 + (ox2[i] * 2 + kx)) * C1_STRIDE + cibeg;
        #pragma unroll 4
        for (int ci4 = 0; ci4 < 32; ci4 += 4) {
            float4 av[4];
            #pragma unroll
            for (int i = 0; i < 4; i++)
                av[i] = *(const float4*)(sm + C1_OFF + pb[i] + ci4);
            const int ciw = cibeg + ci4;   // absolute weight row
            CONV2_STEP(0, x)
            CONV2_STEP(1, y)
            CONV2_STEP(2, z)
            CONV2_STEP(3, w)
        }
    }
    __syncthreads();   // all conv2 C1 reads done before partial writes reuse C1
    // write K-split partials into the (now dead) c1 region: 4 x 2048
    #pragma unroll
    for (int i = 0; i < 4; i++) {
        int px = pg2 * 4 + i;
        float* dst = sm + C1_OFF + ks * 2048 + px * 128 + co2;
        #pragma unroll
        for (int jp = 0; jp < 4; jp++) {
            float v0, v1; unpack2(ac2[i][jp], v0, v1);
            dst[2 * jp] = v0; dst[2 * jp + 1] = v1;
        }
    }
    __syncthreads();
    {   // reduce + bias + relu -> flattened conv2 output in global
        float* c2out = g_c2 + (size_t)box * 2048;
        #pragma unroll
        for (int r = 0; r < 8; r++) {
            int o = t * 8 + r;
            float v = sm[C1_OFF + o] + sm[C1_OFF + 2048 + o]
                    + sm[C1_OFF + 4096 + o] + sm[C1_OFF + 6144 + o] + c2b[o & 127];
            c2out[o] = fmaxf(v, 0.f);
        }
    }
}

// ---------- kernel 2/3: tiled GEMM + bias + relu (BM=BN=128, BK=16, 8x8 thread tile)
//           with register double-buffered k-loop (global loads hidden under compute) ----------
__global__ __launch_bounds__(256)
void gemm_bias_relu(const float* __restrict__ A, const float* __restrict__ W,
                    const float* __restrict__ bias, float* __restrict__ C,
                    int M, int K, int N)
{
    __shared__ __align__(16) float As[16][128];
    __shared__ __align__(16) float Bs[16][128];
    const int t = threadIdx.x;
    const int m0 = blockIdx.y * 128, n0 = blockIdx.x * 128;
    // square warp footprint: 8 m-groups x 4 n-groups per warp
    const int lane = t & 31, wrp = t >> 5;
    const int tm = (lane & 7) | ((wrp & 1) << 3);
    const int tn = (lane >> 3) | ((wrp >> 1) << 2);

    // global-load indices (fixed per thread)
    const int a_row = t >> 2, a_kq = (t & 3) * 4;   // q0: rows 0..63; q1: rows 64..127 (same kq)
    int rg1 = m0 + a_row;      if (rg1 >= M) rg1 = M - 1;
    int rg2 = m0 + a_row + 64; if (rg2 >= M) rg2 = M - 1;
    const int b_r = t >> 5, b_nc = (t & 31) * 4;    // q0: rows 0..7; q1: rows 8..15

    ULL acc[8][4];
    #pragma unroll
    for (int m = 0; m < 8; m++)
        #pragma unroll
        for (int p = 0; p < 4; p++) acc[m][p] = 0ull;

    // prologue: stage k0=0 into registers
    float4 va0 = *(const float4*)(A + (size_t)rg1 * K + a_kq);
    float4 va1 = *(const float4*)(A + (size_t)rg2 * K + a_kq);
    float4 vb0 = *(const float4*)(W + (size_t)b_r * N + n0 + b_nc);
    float4 vb1 = *(const float4*)(W + (size_t)(b_r + 8) * N + n0 + b_nc);

    for (int k0 = 0; k0 < K; k0 += 16) {
        __syncthreads();   // previous compute done reading smem
        As[a_kq + 0][a_row] = va0.x; As[a_kq + 1][a_row] = va0.y;
        As[a_kq + 2][a_row] = va0.z; As[a_kq + 3][a_row] = va0.w;
        As[a_kq + 0][a_row + 64] = va1.x; As[a_kq + 1][a_row + 64] = va1.y;
        As[a_kq + 2][a_row + 64] = va1.z; As[a_kq + 3][a_row + 64] = va1.w;
        *(float4*)&Bs[b_r][b_nc] = vb0;
        *(float4*)&Bs[b_r + 8][b_nc] = vb1;
        __syncthreads();
        if (k0 + 16 < K) {   // issue next-block loads; they complete under compute
            const int k1 = k0 + 16;
            va0 = *(const float4*)(A + (size_t)rg1 * K + k1 + a_kq);
            va1 = *(const float4*)(A + (size_t)rg2 * K + k1 + a_kq);
            vb0 = *(const float4*)(W + (size_t)(k1 + b_r) * N + n0 + b_nc);
            vb1 = *(const float4*)(W + (size_t)(k1 + b_r + 8) * N + n0 + b_nc);
        }
        #pragma unroll
        for (int k = 0; k < 16; k++) {
            float4 a0 = *(const float4*)&As[k][tm * 8];
            float4 a1 = *(const float4*)&As[k][tm * 8 + 4];
            const ulonglong2* bp = (const ulonglong2*)&Bs[k][tn * 8];
            ulonglong2 bA = bp[0], bB = bp[1];
            ULL am[8];
            am[0] = dup2(a0.x); am[1] = dup2(a0.y); am[2] = dup2(a0.z); am[3] = dup2(a0.w);
            am[4] = dup2(a1.x); am[5] = dup2(a1.y); am[6] = dup2(a1.z); am[7] = dup2(a1.w);
            #pragma unroll
            for (int m = 0; m < 8; m++) {
                acc[m][0] = fma2(am[m], bA.x, acc[m][0]);
                acc[m][1] = fma2(am[m], bA.y, acc[m][1]);
                acc[m][2] = fma2(am[m], bB.x, acc[m][2]);
                acc[m][3] = fma2(am[m], bB.y, acc[m][3]);
            }
        }
    }
    float bn[8];
    #pragma unroll
    for (int p = 0; p < 8; p++) bn[p] = bias[n0 + tn * 8 + p];
    #pragma unroll
    for (int m = 0; m < 8; m++) {
        int row = m0 + tm * 8 + m;
        if (row < M) {
            float* crow = C + (size_t)row * N + n0 + tn * 8;
            #pragma unroll
            for (int p = 0; p < 4; p++) {
                float v0, v1; unpack2(acc[m][p], v0, v1);
                crow[2 * p]     = fmaxf(v0 + bn[2 * p], 0.f);
                crow[2 * p + 1] = fmaxf(v1 + bn[2 * p + 1], 0.f);
            }
        }
    }
}

// ---------- kernel 4: heads (reg/score projections, class gather, box decode) ----------
__global__ __launch_bounds__(128)
void heads_kernel(const float* __restrict__ bboxes, const int* __restrict__ cls,
                  const float* __restrict__ reg_w, const float* __restrict__ reg_b,
                  const float* __restrict__ score_w, const float* __restrict__ score_b,
                  float* __restrict__ out, int N)
{
    __shared__ float h[512];
    __shared__ float ob[16];
    const int box = blockIdx.x;
    const int t = threadIdx.x;
    const float* hrow = g_h2 + (size_t)box * 512;
    *(float4*)&h[t * 4] = *(const float4*)&hrow[t * 4];
    __syncthreads();

    const int w = t >> 5, l = t & 31;
    #pragma unroll
    for (int r = 0; r < 4; r++) {
        int o = w + r * 4;
        if (o < 15) {
            float s = 0.f;
            if (o < 12) {
                for (int k = l; k < 512; k += 32) s += h[k] * reg_w[k * 12 + o];
            } else {
                int oc = o - 12;
                for (int k = l; k < 512; k += 32) s += h[k] * score_w[k * 3 + oc];
            }
            #pragma unroll
            for (int d = 16; d; d >>= 1) s += __shfl_xor_sync(0xffffffffu, s, d);
            if (l == 0) ob[o] = s + (o < 12 ? reg_b[o] : score_b[o - 12]);
        }
    }
    __syncthreads();
    if (t == 0) {
        int c = cls[box];
        float d0 = ob[c * 4 + 0], d1 = ob[c * 4 + 1];
        float d2 = ob[c * 4 + 2], d3 = ob[c * 4 + 3];
        float sc = ob[12 + c];
        float y1 = bboxes[box * 4 + 0], x1 = bboxes[box * 4 + 1];
        float y2 = bboxes[box * 4 + 2], x2 = bboxes[box * 4 + 3];
        float hh = y2 - y1, ww = x2 - x1;
        float cy = y1 + 0.5f * hh + d0 * hh;
        float cx = x1 + 0.5f * ww + d1 * ww;
        float nh = hh * expf(d2);
        float nw = ww * expf(d3);
        out[box] = sc;                       // regression_scores [N,1]
        float* rg = out + N;                 // regressions [N,4]
        rg[box * 4 + 0] = d0; rg[box * 4 + 1] = d1;
        rg[box * 4 + 2] = d2; rg[box * 4 + 3] = d3;
        float* bb = out + (size_t)N * 5;     // regression_bboxes [N,4]
        bb[box * 4 + 0] = cy - 0.5f * nh;
        bb[box * 4 + 1] = cx - 0.5f * nw;
        bb[box * 4 + 2] = cy + 0.5f * nh;
        bb[box * 4 + 3] = cx + 0.5f * nw;
    }
}

// ---------- host launcher ----------
extern "C" void kernel_launch(void* const* d_in, const int* in_sizes, int n_in,
                              void* d_out, int out_size)
{
    const float* features = (const float*)d_in[0];
    const float* proposal = (const float*)d_in[1];
    const float* bboxes   = (const float*)d_in[2];
    const int*   box_idx  = (const int*)d_in[3];
    const int*   cls      = (const int*)d_in[4];
    const float* c1w = (const float*)d_in[5];
    const float* c1b = (const float*)d_in[6];
    const float* c2w = (const float*)d_in[7];
    const float* c2b = (const float*)d_in[8];
    const float* d1w = (const float*)d_in[9];
    const float* d1b = (const float*)d_in[10];
    const float* d2w = (const float*)d_in[11];
    const float* d2b = (const float*)d_in[12];
    const float* rgw = (const float*)d_in[13];
    const float* rgb = (const float*)d_in[14];
    const float* scw = (const float*)d_in[15];
    const float* scb = (const float*)d_in[16];
    float* out = (float*)d_out;

    const int N = in_sizes[2] / 4;  // number of boxes

    void *p_c2 = nullptr, *p_h1 = nullptr, *p_h2 = nullptr;
    cudaGetSymbolAddress(&p_c2, g_c2);
    cudaGetSymbolAddress(&p_h1, g_h1);
    cudaGetSymbolAddress(&p_h2, g_h2);

    cudaFuncSetAttribute(crop_conv_kernel,
                         cudaFuncAttributeMaxDynamicSharedMemorySize, SMEM_BYTES);

    crop_conv_kernel<<<N, 256, SMEM_BYTES>>>(features, proposal, bboxes, box_idx,
                                             c1w, c1b, c2w, c2b);

    dim3 g1(512 / 128, (N + 127) / 128);
    gemm_bias_relu<<<g1, 256>>>((const float*)p_c2, d1w, d1b, (float*)p_h1,
                                N, 2048, 512);

    dim3 g2(512 / 128, (N + 127) / 128);
    gemm_bias_relu<<<g2, 256>>>((const float*)p_h1, d2w, d2b, (float*)p_h2,
                                N, 512, 512);

    heads_kernel<<<N, 128>>>(bboxes, cls, rgw, rgb, scw, scb, out, N);
}